// round 16
// baseline (speedup 1.0000x reference)
#include <cuda_runtime.h>
#include <cstdint>

// Problem dims
#define NB 32
#define C  64
#define H  128
#define W  128
#define CO 64
#define HO 64
#define WO 64

// Scratch: packed sign bits.
__device__ uint64_t g_xpack[NB * H * W];          // 4 MiB (L2-resident)
__device__ uint64_t g_wpack[CO * 9];

// ---------------------------------------------------------------------------
// Kernel 1: pack x AND w sign bits (R9 winner, unchanged).
// ---------------------------------------------------------------------------
__global__ __launch_bounds__(256) void pack_kernel(const float* __restrict__ x,
                                                   const float* __restrict__ w) {
    if (blockIdx.x >= 1024) {
        int t = (blockIdx.x - 1024) * 36 + threadIdx.x;
        if (threadIdx.x < 36 && t < CO * 9) {
            int co = t / 9;
            int k  = t - co * 9;
            uint32_t lo = 0, hi = 0;
            #pragma unroll 8
            for (int ci = 0; ci < 32; ++ci)
                lo |= (uint32_t)(w[(size_t)(co * 64 + ci) * 9 + k] >= 0.0f) << ci;
            #pragma unroll 8
            for (int ci = 0; ci < 32; ++ci)
                hi |= (uint32_t)(w[(size_t)(co * 64 + ci + 32) * 9 + k] >= 0.0f) << ci;
            g_wpack[t] = (uint64_t)lo | ((uint64_t)hi << 32);
        }
        return;
    }

    int tid = blockIdx.x * blockDim.x + threadIdx.x;   // 0 .. 262143
    int w2 = tid & 63;
    int h  = (tid >> 6) & 127;
    int n  = tid >> 13;

    const float* base = x + (size_t)n * C * (H * W) + h * W + w2 * 2;

    uint32_t lo0 = 0, lo1 = 0, hi0 = 0, hi1 = 0;

    #pragma unroll 16
    for (int c = 0; c < 32; ++c) {
        float2 v = __ldcs(reinterpret_cast<const float2*>(base + (size_t)c * (H * W)));
        lo0 |= (uint32_t)(v.x >= 0.0f) << c;
        lo1 |= (uint32_t)(v.y >= 0.0f) << c;
    }
    #pragma unroll 16
    for (int c = 0; c < 32; ++c) {
        float2 v = __ldcs(reinterpret_cast<const float2*>(base + (size_t)(c + 32) * (H * W)));
        hi0 |= (uint32_t)(v.x >= 0.0f) << c;
        hi1 |= (uint32_t)(v.y >= 0.0f) << c;
    }

    uint64_t* op = g_xpack + ((size_t)n * H + h) * W + w2 * 2;
    op[0] = (uint64_t)lo0 | ((uint64_t)hi0 << 32);
    op[1] = (uint64_t)lo1 | ((uint64_t)hi1 << 32);
}

// ---------------------------------------------------------------------------
// Kernel 2: broadcast-conv (weights in per-lane registers, pixel words via
// warp-uniform LDS) — now occupancy-capped: __launch_bounds__(256, 6)
// forces <=42 regs -> 6 CTAs/SM (occ 54% -> ~75%), and the accumulator is
// split into two independent chains (lo/hi) to halve serial IADD depth.
// Block = 1 output row x 64 wo x 64 co; lane owns one co.
// ---------------------------------------------------------------------------
__global__ __launch_bounds__(256, 6) void qconv_bcast_kernel(float* __restrict__ out) {
    const int PW = 132;
    __shared__ uint64_t sp[3 * PW];        // 3168 B: 3 input rows, cols -1..127
    __shared__ float sbuf[64 * 65];        // 16640 B: [wo][co] padded

    int n   = blockIdx.y;
    int ho  = blockIdx.x;
    int iy0 = 2 * ho - 1;
    int tid = threadIdx.x;
    int wid = tid >> 5;
    int lane = tid & 31;
    int co  = ((wid >= 4) ? 32 : 0) + lane;

    // Per-lane weights -> registers (once per block; g_wpack is L2-hot)
    uint32_t wlo[9], whi[9];
    #pragma unroll
    for (int t = 0; t < 9; ++t) {
        uint64_t wv = g_wpack[co * 9 + t];
        wlo[t] = (uint32_t)wv;
        whi[t] = (uint32_t)(wv >> 32);
    }

    // Stage 3x129 packed input rows from g_xpack (L2 hits)
    for (int i = tid; i < 3 * 129; i += 256) {
        int r  = i / 129;
        int cx = i - r * 129;
        int iy = iy0 + r;
        int ix = cx - 1;
        uint64_t v = 0;
        if (iy >= 0 && ix >= 0)
            v = g_xpack[((size_t)n * H + iy) * W + ix];
        sp[r * PW + cx] = v;
    }
    __syncthreads();

    int px0 = (wid & 3) * 16;              // this warp's 16 wo positions
    uint32_t mr = (ho > 0) ? 0xFFFFFFFFu : 0u;
    int rowsv = (ho > 0) ? 3 : 2;

    #pragma unroll 4
    for (int u = 0; u < 16; ++u) {
        int tx = px0 + u;
        uint32_t mc = (tx > 0) ? 0xFFFFFFFFu : 0u;
        uint32_t mb = mr & mc;
        int base = 64 * rowsv * (tx > 0 ? 3 : 2);

        // Two independent accumulator chains (lo words / hi words)
        int accL = 0, accH = 0;
        #pragma unroll
        for (int ky = 0; ky < 3; ++ky) {
            uint64_t s0 = sp[ky * PW + 2 * tx + 0];   // warp-uniform broadcast
            uint64_t s1 = sp[ky * PW + 2 * tx + 1];
            uint64_t s2 = sp[ky * PW + 2 * tx + 2];
            uint32_t m0  = (ky == 0) ? mb : mc;        // kx==0 tap
            uint32_t m12 = (ky == 0) ? mr : 0xFFFFFFFFu;
            int t = ky * 3;
            accL += __popc(((uint32_t)s0 ^ wlo[t])     & m0);
            accH += __popc(((uint32_t)(s0 >> 32) ^ whi[t]) & m0);
            accL += __popc(((uint32_t)s1 ^ wlo[t + 1]) & m12);
            accH += __popc(((uint32_t)(s1 >> 32) ^ whi[t + 1]) & m12);
            accL += __popc(((uint32_t)s2 ^ wlo[t + 2]) & m12);
            accH += __popc(((uint32_t)(s2 >> 32) ^ whi[t + 2]) & m12);
        }
        sbuf[tx * 65 + co] = (float)(base - 2 * (accL + accH));
    }
    __syncthreads();

    // Coalesced store: consecutive threads -> consecutive wo within a co plane
    const size_t plane = (size_t)HO * WO;
    float* ob = out + ((size_t)n * CO) * plane + (size_t)ho * WO;
    for (int e = tid; e < 64 * 64; e += 256) {
        int c2 = e >> 6;
        int wo = e & 63;
        ob[(size_t)c2 * plane + wo] = sbuf[wo * 65 + c2];   // stride-65: conflict-free
    }
}

// ---------------------------------------------------------------------------
extern "C" void kernel_launch(void* const* d_in, const int* in_sizes, int n_in,
                              void* d_out, int out_size) {
    const float* x = (const float*)d_in[0];
    const float* w = (const float*)d_in[1];
    float* out = (float*)d_out;

    pack_kernel<<<1040, 256>>>(x, w);
    qconv_bcast_kernel<<<dim3(HO, NB), 256>>>(out);
}